// round 5
// baseline (speedup 1.0000x reference)
#include <cuda_runtime.h>

#define BB 2048
#define QROWS 2080   // 2048 padded + prefetch margin; rows >= T stay zero

// FIR pre-pass output: qx[t,i] = (x[t,i]-b_act)/max_current. Zero-initialized;
// fir_kernel writes only rows t < T, so padding rows are always 0.
__device__ float g_qx[QROWS * BB];
// dump target for non-writer lanes' unconditional stores (never read)
__device__ float g_dump[64 * BB];

// ---------------------------------------------------------------------------
// Kernel A: FIR pre-pass (unchanged)
// ---------------------------------------------------------------------------
__global__ void __launch_bounds__(64) fir_kernel(
    const float* __restrict__ cur,
    const float* __restrict__ a,
    const float* __restrict__ b_act,
    const float* __restrict__ max_cur,
    int T)
{
    __shared__ float sm[127][64];
    const int li = threadIdx.x;
    const int i  = blockIdx.x * 64 + li;
    const int t0 = blockIdx.y * 64;

    float areg[64];
#pragma unroll
    for (int k = 0; k < 64; ++k) areg[k] = __ldg(&a[k]);
    const float bact   = __ldg(&b_act[0]);
    const float inv_mc = 1.0f / __ldg(&max_cur[0]);

#pragma unroll 1
    for (int rr = 0; rr < 127; ++rr) {
        int s = t0 - 63 + rr;
        sm[rr][li] = (s >= 0 && s < T) ? __ldg(&cur[(size_t)s * BB + i]) : 0.0f;
    }
    __syncthreads();

#pragma unroll 1
    for (int tt = 0; tt < 64; tt += 4) {
        float a0 = 0.f, a1 = 0.f, a2 = 0.f, a3 = 0.f;
#pragma unroll
        for (int rr = 0; rr < 67; ++rr) {
            float v = sm[tt + rr][li];
            if (rr <= 63)            a0 = fmaf(areg[rr],     v, a0);
            if (rr >= 1 && rr <= 64) a1 = fmaf(areg[rr - 1], v, a1);
            if (rr >= 2 && rr <= 65) a2 = fmaf(areg[rr - 2], v, a2);
            if (rr >= 3)             a3 = fmaf(areg[rr - 3], v, a3);
        }
        int t = t0 + tt;
        if (t + 0 < T) g_qx[(size_t)(t + 0) * BB + i] = (a0 - bact) * inv_mc;
        if (t + 1 < T) g_qx[(size_t)(t + 1) * BB + i] = (a1 - bact) * inv_mc;
        if (t + 2 < T) g_qx[(size_t)(t + 2) * BB + i] = (a2 - bact) * inv_mc;
        if (t + 3 < T) g_qx[(size_t)(t + 3) * BB + i] = (a3 - bact) * inv_mc;
    }
}

// ---------------------------------------------------------------------------
// Kernel B: 4 lanes/element, systolic ring, SHFL-free serial chain.
// Lane r owns taps j=16r+1..16r+16 in ring R[16]. Lane0's released slot R[p]
// is the COMPLETE y(t) -> f computed locally on lane0 (lanes 1-3 compute a
// finite don't-care). Critical tap-1 update uses per-lane weight W0z
// ({W[0],0,0,0}) with f_local -> the f->f chain is ALU/MUFU only (~60 cyc).
// True f is then broadcast (shfl, off-chain: consumers have >=2-step slack);
// lanes 1-3's tap-(16r+1) is restored via complementary weight W0b.
// Hand-off: released slot value passes down one lane (shfl_down) as the seed
// for the overwrite slot (target p+16) -> 16-step slack.
// ---------------------------------------------------------------------------
#define STEP(p) { \
    float val_ = R[(p)&15]; \
    float hU_  = __shfl_down_sync(0xffffffffu, val_, 1, 4); \
    float U_   = (r == 3) ? 0.0f : hU_; \
    float xx_  = val_ + q[(p)&7]; \
    q[(p)&7]   = __ldg(qb + (size_t)(p) * BB); \
    float u_   = xx_ * xx_; \
    float s1_  = fmaf(c1, xx_, c0); \
    float s2_  = fmaf(c3, xx_, c2); \
    float pv_  = fmaf(u_, s2_, s1_); \
    float ev_; asm("ex2.approx.f32 %0, %1;" : "=f"(ev_) : "f"(pv_)); \
    float dn_  = ev_ + 1.0f; \
    float rc_; asm("rcp.approx.f32 %0, %1;" : "=f"(rc_) : "f"(dn_)); \
    float f_   = fmaxf(0.0f, fmaf(neg2mfr, rc_, mfr)); \
    /* CRITICAL: tap-1 update with local f (W0z==0 on lanes 1-3) */ \
    R[((p)+ 1)&15] = fmaf(W0z, f_, R[((p)+ 1)&15]); \
    /* broadcast true f (off the serial chain from here on) */ \
    float fb_  = __shfl_sync(0xffffffffu, f_, 0, 4); \
    obase[(size_t)(p) * BB] = f_; \
    R[((p)+ 1)&15] = fmaf(W0b,  fb_, R[((p)+ 1)&15]); \
    R[((p)+ 2)&15] = fmaf(W[ 1], fb_, R[((p)+ 2)&15]); \
    R[((p)+ 3)&15] = fmaf(W[ 2], fb_, R[((p)+ 3)&15]); \
    R[((p)+ 4)&15] = fmaf(W[ 3], fb_, R[((p)+ 4)&15]); \
    R[((p)+ 5)&15] = fmaf(W[ 4], fb_, R[((p)+ 5)&15]); \
    R[((p)+ 6)&15] = fmaf(W[ 5], fb_, R[((p)+ 6)&15]); \
    R[((p)+ 7)&15] = fmaf(W[ 6], fb_, R[((p)+ 7)&15]); \
    R[((p)+ 8)&15] = fmaf(W[ 7], fb_, R[((p)+ 8)&15]); \
    R[((p)+ 9)&15] = fmaf(W[ 8], fb_, R[((p)+ 9)&15]); \
    R[((p)+10)&15] = fmaf(W[ 9], fb_, R[((p)+10)&15]); \
    R[((p)+11)&15] = fmaf(W[10], fb_, R[((p)+11)&15]); \
    R[((p)+12)&15] = fmaf(W[11], fb_, R[((p)+12)&15]); \
    R[((p)+13)&15] = fmaf(W[12], fb_, R[((p)+13)&15]); \
    R[((p)+14)&15] = fmaf(W[13], fb_, R[((p)+14)&15]); \
    R[((p)+15)&15] = fmaf(W[14], fb_, R[((p)+15)&15]); \
    R[(p)&15]      = fmaf(W[15], fb_, U_); \
}

#define S16() STEP(0) STEP(1) STEP(2) STEP(3) STEP(4) STEP(5) STEP(6) STEP(7) \
              STEP(8) STEP(9) STEP(10) STEP(11) STEP(12) STEP(13) STEP(14) STEP(15)

__global__ void __launch_bounds__(128) rec_kernel(
    const float* __restrict__ b_lag,
    const float* __restrict__ poly_coeff,
    const float* __restrict__ max_cur,
    const float* __restrict__ max_fr,
    float* __restrict__ out,
    int T)
{
    const int lane = threadIdx.x;
    const int r    = lane & 3;                       // lane within 4-lane group
    const int e    = blockIdx.x * 32 + (lane >> 2);  // element index

    const float inv_mc = 1.0f / __ldg(&max_cur[0]);
    const float mfr    = __ldg(&max_fr[0]);
    const float TWO_LOG2E = 2.8853900817779268f;     // 2*log2(e) folded into coeffs
    float c0 = __ldg(&poly_coeff[0]); c0 = c0 * c0 * TWO_LOG2E;
    float c1 = __ldg(&poly_coeff[1]); c1 = c1 * c1 * TWO_LOG2E;
    float c2 = __ldg(&poly_coeff[2]); c2 = c2 * c2 * TWO_LOG2E;
    float c3 = __ldg(&poly_coeff[3]); c3 = c3 * c3 * TWO_LOG2E;
    const float cw      = 1000.0f * inv_mc;
    const float neg2mfr = -2.0f * mfr;

    // lane r owns taps j = 16r+d (d=1..16); weight = cw * b_lag[64 - j]
    float W[16];
#pragma unroll
    for (int d = 1; d <= 16; ++d) W[d - 1] = cw * __ldg(&b_lag[64 - 16 * r - d]);

    // split tap-(16r+1) weight: W0z acts on f_local (lane0 only), W0b on f_bcast
    const float W0z = (r == 0) ? W[0] : 0.0f;
    const float W0b = (r == 0) ? 0.0f : W[0];

    float R[16];
#pragma unroll
    for (int k = 0; k < 16; ++k) R[k] = 0.0f;

    // 8-deep qx prefetch ring
    float q[8];
#pragma unroll
    for (int d = 0; d < 8; ++d) q[d] = __ldg(g_qx + e + (size_t)d * BB);

    // lane0 of each group writes real output; others store to dump (no branches)
    float* obase = (r == 0) ? (out + e) : (g_dump + e);
    const size_t ostep = (r == 0) ? (size_t)16 * BB : 0;

    const int nfull = T >> 4;
    for (int blk = 0; blk < nfull; ++blk) {
        const float* qb = g_qx + e + (size_t)(blk * 16 + 8) * BB;
        S16()
        obase += ostep;
    }

    // ---- generic tail (T mod 16 steps): slow dynamic-index path ----
    const int t0tail = nfull * 16;
    const int tail   = T - t0tail;
    if (tail > 0) {
        float ringD[16];
#pragma unroll
        for (int k = 0; k < 16; ++k) ringD[k] = R[k];
#pragma unroll 1
        for (int tt = 0; tt < tail; ++tt) {
            int t = t0tail + tt;
            int p = t & 15;
            float val = ringD[p];
            float hU  = __shfl_down_sync(0xffffffffu, val, 1, 4);
            float U   = (r == 3) ? 0.0f : hU;
            float xx  = val + __ldg(g_qx + e + (size_t)t * BB);
            float u_  = xx * xx;
            float s1_ = fmaf(c1, xx, c0);
            float s2_ = fmaf(c3, xx, c2);
            float pv  = fmaf(u_, s2_, s1_);
            float ev; asm("ex2.approx.f32 %0, %1;" : "=f"(ev) : "f"(pv));
            float dn = ev + 1.0f;
            float rc; asm("rcp.approx.f32 %0, %1;" : "=f"(rc) : "f"(dn));
            float f = fmaxf(0.0f, fmaf(neg2mfr, rc, mfr));
            float fb = __shfl_sync(0xffffffffu, f, 0, 4);
            if (r == 0) out[(size_t)t * BB + e] = f;
            ringD[(p + 1) & 15] = fmaf(W0z, f,  ringD[(p + 1) & 15]);
            ringD[(p + 1) & 15] = fmaf(W0b, fb, ringD[(p + 1) & 15]);
#pragma unroll 1
            for (int d = 2; d <= 15; ++d)
                ringD[(p + d) & 15] = fmaf(W[d - 1], fb, ringD[(p + d) & 15]);
            ringD[p] = fmaf(W[15], fb, U);
        }
    }
}

// ---------------------------------------------------------------------------
extern "C" void kernel_launch(void* const* d_in, const int* in_sizes, int n_in,
                              void* d_out, int out_size)
{
    const float* currents = (const float*)d_in[0];
    const float* a        = (const float*)d_in[1];
    const float* b_lag    = (const float*)d_in[2];
    const float* poly     = (const float*)d_in[3];
    const float* b_act    = (const float*)d_in[4];
    const float* max_cur  = (const float*)d_in[5];
    const float* max_fr   = (const float*)d_in[6];
    float* out = (float*)d_out;

    const int T = in_sizes[0] / BB;   // 2000

    dim3 gA(BB / 64, (T + 63) / 64);
    fir_kernel<<<gA, 64>>>(currents, a, b_act, max_cur, T);

    // 4 lanes/element, 32 elements per 128-thread block -> 64 blocks
    rec_kernel<<<BB / 32, 128>>>(b_lag, poly, max_cur, max_fr, out, T);
}

// round 6
// speedup vs baseline: 1.2162x; 1.2162x over previous
#include <cuda_runtime.h>

#define BB    2048
#define TR    2080   // row length of transposed qx (floats); rows zero-padded
#define TROUT 2048   // row length of transposed output

// transposed FIR output: g_qxT[e*TR + t] = (x[t,e]-b_act)/max_current
__device__ float g_qxT[(size_t)BB * TR];
// transposed recurrence output: g_outT[e*TROUT + t] = f[t,e]
__device__ float g_outT[(size_t)BB * TROUT];

// ---------------------------------------------------------------------------
// Kernel A: FIR pre-pass, writes TRANSPOSED qx (thread owns one column e ->
// its 4 consecutive-in-t outputs form one st.v4 to row e).
// ---------------------------------------------------------------------------
__global__ void __launch_bounds__(64) fir_kernel(
    const float* __restrict__ cur,
    const float* __restrict__ a,
    const float* __restrict__ b_act,
    const float* __restrict__ max_cur,
    int T)
{
    __shared__ float sm[127][64];
    const int li = threadIdx.x;
    const int i  = blockIdx.x * 64 + li;
    const int t0 = blockIdx.y * 64;

    float areg[64];
#pragma unroll
    for (int k = 0; k < 64; ++k) areg[k] = __ldg(&a[k]);
    const float bact   = __ldg(&b_act[0]);
    const float inv_mc = 1.0f / __ldg(&max_cur[0]);

#pragma unroll 1
    for (int rr = 0; rr < 127; ++rr) {
        int s = t0 - 63 + rr;
        sm[rr][li] = (s >= 0 && s < T) ? __ldg(&cur[(size_t)s * BB + i]) : 0.0f;
    }
    __syncthreads();

    float* myrow = g_qxT + (size_t)i * TR;

#pragma unroll 1
    for (int tt = 0; tt < 64; tt += 4) {
        float a0 = 0.f, a1 = 0.f, a2 = 0.f, a3 = 0.f;
#pragma unroll
        for (int rr = 0; rr < 67; ++rr) {
            float v = sm[tt + rr][li];
            if (rr <= 63)            a0 = fmaf(areg[rr],     v, a0);
            if (rr >= 1 && rr <= 64) a1 = fmaf(areg[rr - 1], v, a1);
            if (rr >= 2 && rr <= 65) a2 = fmaf(areg[rr - 2], v, a2);
            if (rr >= 3)             a3 = fmaf(areg[rr - 3], v, a3);
        }
        int t = t0 + tt;
        float v0 = (a0 - bact) * inv_mc, v1 = (a1 - bact) * inv_mc;
        float v2 = (a2 - bact) * inv_mc, v3 = (a3 - bact) * inv_mc;
        if (t + 3 < T) {
            *(float4*)(myrow + t) = make_float4(v0, v1, v2, v3);
        } else {
            if (t + 0 < T) myrow[t + 0] = v0;
            if (t + 1 < T) myrow[t + 1] = v1;
            if (t + 2 < T) myrow[t + 2] = v2;
            if (t + 3 < T) myrow[t + 3] = v3;
        }
    }
}

// ---------------------------------------------------------------------------
// Kernel B: 4 lanes/element systolic ring (as R5), but ZERO per-step memory:
// q values come from a 16-reg buffer filled by 4x LDG.128 per 16-step block
// (issued a full block ahead), f values buffered in 16 regs and written as
// 4x STG.128 per block (lane0 only, to transposed g_outT).
// ---------------------------------------------------------------------------
#define STEP(p) { \
    float val_ = R[(p)&15]; \
    float hU_  = __shfl_down_sync(0xffffffffu, val_, 1, 4); \
    float U_   = (r == 3) ? 0.0f : hU_; \
    float xx_  = val_ + qf[(p)&15]; \
    float u_   = xx_ * xx_; \
    float s1_  = fmaf(c1, xx_, c0); \
    float s2_  = fmaf(c3, xx_, c2); \
    float pv_  = fmaf(u_, s2_, s1_); \
    float ev_; asm("ex2.approx.f32 %0, %1;" : "=f"(ev_) : "f"(pv_)); \
    float dn_  = ev_ + 1.0f; \
    float rc_; asm("rcp.approx.f32 %0, %1;" : "=f"(rc_) : "f"(dn_)); \
    float f_   = fmaxf(0.0f, fmaf(neg2mfr, rc_, mfr)); \
    /* CRITICAL: tap-1 with local f (W0z==0 on lanes 1-3) */ \
    R[((p)+ 1)&15] = fmaf(W0z, f_, R[((p)+ 1)&15]); \
    float fb_  = __shfl_sync(0xffffffffu, f_, 0, 4); \
    fbv[(p)&15] = f_; \
    R[((p)+ 1)&15] = fmaf(W0b,  fb_, R[((p)+ 1)&15]); \
    R[((p)+ 2)&15] = fmaf(W[ 1], fb_, R[((p)+ 2)&15]); \
    R[((p)+ 3)&15] = fmaf(W[ 2], fb_, R[((p)+ 3)&15]); \
    R[((p)+ 4)&15] = fmaf(W[ 3], fb_, R[((p)+ 4)&15]); \
    R[((p)+ 5)&15] = fmaf(W[ 4], fb_, R[((p)+ 5)&15]); \
    R[((p)+ 6)&15] = fmaf(W[ 5], fb_, R[((p)+ 6)&15]); \
    R[((p)+ 7)&15] = fmaf(W[ 6], fb_, R[((p)+ 7)&15]); \
    R[((p)+ 8)&15] = fmaf(W[ 7], fb_, R[((p)+ 8)&15]); \
    R[((p)+ 9)&15] = fmaf(W[ 8], fb_, R[((p)+ 9)&15]); \
    R[((p)+10)&15] = fmaf(W[ 9], fb_, R[((p)+10)&15]); \
    R[((p)+11)&15] = fmaf(W[10], fb_, R[((p)+11)&15]); \
    R[((p)+12)&15] = fmaf(W[11], fb_, R[((p)+12)&15]); \
    R[((p)+13)&15] = fmaf(W[12], fb_, R[((p)+13)&15]); \
    R[((p)+14)&15] = fmaf(W[13], fb_, R[((p)+14)&15]); \
    R[((p)+15)&15] = fmaf(W[14], fb_, R[((p)+15)&15]); \
    R[(p)&15]      = fmaf(W[15], fb_, U_); \
}

#define S16() STEP(0) STEP(1) STEP(2) STEP(3) STEP(4) STEP(5) STEP(6) STEP(7) \
              STEP(8) STEP(9) STEP(10) STEP(11) STEP(12) STEP(13) STEP(14) STEP(15)

__global__ void __launch_bounds__(128) rec_kernel(
    const float* __restrict__ b_lag,
    const float* __restrict__ poly_coeff,
    const float* __restrict__ max_cur,
    const float* __restrict__ max_fr,
    int T)
{
    const int lane = threadIdx.x;
    const int r    = lane & 3;
    const int e    = blockIdx.x * 32 + (lane >> 2);

    const float inv_mc = 1.0f / __ldg(&max_cur[0]);
    const float mfr    = __ldg(&max_fr[0]);
    const float TWO_LOG2E = 2.8853900817779268f;
    float c0 = __ldg(&poly_coeff[0]); c0 = c0 * c0 * TWO_LOG2E;
    float c1 = __ldg(&poly_coeff[1]); c1 = c1 * c1 * TWO_LOG2E;
    float c2 = __ldg(&poly_coeff[2]); c2 = c2 * c2 * TWO_LOG2E;
    float c3 = __ldg(&poly_coeff[3]); c3 = c3 * c3 * TWO_LOG2E;
    const float cw      = 1000.0f * inv_mc;
    const float neg2mfr = -2.0f * mfr;

    // lane r owns taps j = 16r+d (d=1..16); weight = cw * b_lag[64 - j]
    float W[16];
#pragma unroll
    for (int d = 1; d <= 16; ++d) W[d - 1] = cw * __ldg(&b_lag[64 - 16 * r - d]);
    const float W0z = (r == 0) ? W[0] : 0.0f;
    const float W0b = (r == 0) ? 0.0f : W[0];

    float R[16];
#pragma unroll
    for (int k = 0; k < 16; ++k) R[k] = 0.0f;

    const float4* qrow = (const float4*)(g_qxT + (size_t)e * TR);
    float* optr = g_outT + (size_t)e * TROUT;   // only lane0 stores

    // current-block q buffer (block 0)
    float qf[16], fbv[16];
    {
        float4 b0 = __ldg(qrow + 0), b1 = __ldg(qrow + 1);
        float4 b2 = __ldg(qrow + 2), b3 = __ldg(qrow + 3);
        qf[0]=b0.x; qf[1]=b0.y; qf[2]=b0.z; qf[3]=b0.w;
        qf[4]=b1.x; qf[5]=b1.y; qf[6]=b1.z; qf[7]=b1.w;
        qf[8]=b2.x; qf[9]=b2.y; qf[10]=b2.z; qf[11]=b2.w;
        qf[12]=b3.x; qf[13]=b3.y; qf[14]=b3.z; qf[15]=b3.w;
    }

    const int nfull = T >> 4;
    for (int blk = 0; blk < nfull; ++blk) {
        // prefetch next block's q (rows zero-padded, always safe)
        float4 n0 = __ldg(qrow + (blk + 1) * 4 + 0);
        float4 n1 = __ldg(qrow + (blk + 1) * 4 + 1);
        float4 n2 = __ldg(qrow + (blk + 1) * 4 + 2);
        float4 n3 = __ldg(qrow + (blk + 1) * 4 + 3);

        S16()

        if (r == 0) {
            *(float4*)(optr +  0) = make_float4(fbv[0],  fbv[1],  fbv[2],  fbv[3]);
            *(float4*)(optr +  4) = make_float4(fbv[4],  fbv[5],  fbv[6],  fbv[7]);
            *(float4*)(optr +  8) = make_float4(fbv[8],  fbv[9],  fbv[10], fbv[11]);
            *(float4*)(optr + 12) = make_float4(fbv[12], fbv[13], fbv[14], fbv[15]);
        }
        optr += 16;

        qf[0]=n0.x; qf[1]=n0.y; qf[2]=n0.z; qf[3]=n0.w;
        qf[4]=n1.x; qf[5]=n1.y; qf[6]=n1.z; qf[7]=n1.w;
        qf[8]=n2.x; qf[9]=n2.y; qf[10]=n2.z; qf[11]=n2.w;
        qf[12]=n3.x; qf[13]=n3.y; qf[14]=n3.z; qf[15]=n3.w;
    }

    // ---- generic tail (T mod 16 steps; T=2000 -> empty, kept for safety) ----
    const int t0tail = nfull * 16;
    const int tail   = T - t0tail;
    if (tail > 0) {
        float ringD[16];
#pragma unroll
        for (int k = 0; k < 16; ++k) ringD[k] = R[k];
#pragma unroll 1
        for (int tt = 0; tt < tail; ++tt) {
            int t = t0tail + tt;
            int p = t & 15;
            float val = ringD[p];
            float hU  = __shfl_down_sync(0xffffffffu, val, 1, 4);
            float U   = (r == 3) ? 0.0f : hU;
            float xx  = val + __ldg(g_qxT + (size_t)e * TR + t);
            float u_  = xx * xx;
            float s1_ = fmaf(c1, xx, c0);
            float s2_ = fmaf(c3, xx, c2);
            float pv  = fmaf(u_, s2_, s1_);
            float ev; asm("ex2.approx.f32 %0, %1;" : "=f"(ev) : "f"(pv));
            float dn = ev + 1.0f;
            float rc; asm("rcp.approx.f32 %0, %1;" : "=f"(rc) : "f"(dn));
            float f = fmaxf(0.0f, fmaf(neg2mfr, rc, mfr));
            float fb = __shfl_sync(0xffffffffu, f, 0, 4);
            if (r == 0) g_outT[(size_t)e * TROUT + t] = f;
            ringD[(p + 1) & 15] = fmaf(W0z, f,  ringD[(p + 1) & 15]);
            ringD[(p + 1) & 15] = fmaf(W0b, fb, ringD[(p + 1) & 15]);
#pragma unroll 1
            for (int d = 2; d <= 15; ++d)
                ringD[(p + d) & 15] = fmaf(W[d - 1], fb, ringD[(p + d) & 15]);
            ringD[p] = fmaf(W[15], fb, U);
        }
    }
}

// ---------------------------------------------------------------------------
// Kernel C: transpose g_outT[e][t] -> out[t][e], smem 32x33 tile, coalesced.
// ---------------------------------------------------------------------------
__global__ void __launch_bounds__(256) tr_kernel(float* __restrict__ out, int T)
{
    __shared__ float tile[32][33];
    const int tx = threadIdx.x, ty = threadIdx.y;   // 32 x 8
    const int e0 = blockIdx.x * 32;
    const int t0 = blockIdx.y * 32;

#pragma unroll
    for (int j = 0; j < 4; ++j) {
        int e = e0 + ty + 8 * j;
        int t = t0 + tx;
        tile[ty + 8 * j][tx] = (t < T) ? g_outT[(size_t)e * TROUT + t] : 0.0f;
    }
    __syncthreads();
#pragma unroll
    for (int j = 0; j < 4; ++j) {
        int t = t0 + ty + 8 * j;
        if (t < T) out[(size_t)t * BB + e0 + tx] = tile[tx][ty + 8 * j];
    }
}

// ---------------------------------------------------------------------------
extern "C" void kernel_launch(void* const* d_in, const int* in_sizes, int n_in,
                              void* d_out, int out_size)
{
    const float* currents = (const float*)d_in[0];
    const float* a        = (const float*)d_in[1];
    const float* b_lag    = (const float*)d_in[2];
    const float* poly     = (const float*)d_in[3];
    const float* b_act    = (const float*)d_in[4];
    const float* max_cur  = (const float*)d_in[5];
    const float* max_fr   = (const float*)d_in[6];
    float* out = (float*)d_out;

    const int T = in_sizes[0] / BB;   // 2000

    dim3 gA(BB / 64, (T + 63) / 64);
    fir_kernel<<<gA, 64>>>(currents, a, b_act, max_cur, T);

    rec_kernel<<<BB / 32, 128>>>(b_lag, poly, max_cur, max_fr, T);

    dim3 gC(BB / 32, (T + 31) / 32);
    tr_kernel<<<gC, dim3(32, 8)>>>(out, T);
}

// round 7
// speedup vs baseline: 1.5489x; 1.2735x over previous
#include <cuda_runtime.h>

#define BB    2048
#define TR    2080   // row length of transposed qx (floats); rows zero-padded
#define TROUT 2048   // row length of transposed output

// transposed FIR output: g_qxT[e*TR + t] = (x[t,e]-b_act)/max_current
__device__ float g_qxT[(size_t)BB * TR];
// transposed recurrence output: g_outT[e*TROUT + t] = f[t,e]
__device__ float g_outT[(size_t)BB * TROUT];

// ---------------------------------------------------------------------------
// Kernel A: FIR pre-pass, transposed output. This round: explicit 8-deep
// LDS prefetch ring (vv) so the 29-cyc LDS latency is software-hidden.
// ---------------------------------------------------------------------------
__global__ void __launch_bounds__(64) fir_kernel(
    const float* __restrict__ cur,
    const float* __restrict__ a,
    const float* __restrict__ b_act,
    const float* __restrict__ max_cur,
    int T)
{
    __shared__ float sm[136][64];      // rows 0..126 data, 127..135 zero pad
    const int li = threadIdx.x;
    const int i  = blockIdx.x * 64 + li;
    const int t0 = blockIdx.y * 64;

    float areg[64];
#pragma unroll
    for (int k = 0; k < 64; ++k) areg[k] = __ldg(&a[k]);
    const float bact   = __ldg(&b_act[0]);
    const float inv_mc = 1.0f / __ldg(&max_cur[0]);

#pragma unroll 1
    for (int rr = 0; rr < 127; ++rr) {
        int s = t0 - 63 + rr;
        sm[rr][li] = (s >= 0 && s < T) ? __ldg(&cur[(size_t)s * BB + i]) : 0.0f;
    }
#pragma unroll
    for (int rr = 127; rr < 136; ++rr) sm[rr][li] = 0.0f;
    __syncthreads();

    float* myrow = g_qxT + (size_t)i * TR;

#pragma unroll 1
    for (int tt = 0; tt < 64; tt += 4) {
        float a0 = 0.f, a1 = 0.f, a2 = 0.f, a3 = 0.f;
        float vv[8];
#pragma unroll
        for (int d = 0; d < 8; ++d) vv[d] = sm[tt + d][li];
#pragma unroll
        for (int rr = 0; rr < 67; ++rr) {
            float v = vv[rr & 7];
            vv[rr & 7] = sm[tt + rr + 8][li];   // prefetch 8 iters ahead
            if (rr <= 63)            a0 = fmaf(areg[rr],     v, a0);
            if (rr >= 1 && rr <= 64) a1 = fmaf(areg[rr - 1], v, a1);
            if (rr >= 2 && rr <= 65) a2 = fmaf(areg[rr - 2], v, a2);
            if (rr >= 3)             a3 = fmaf(areg[rr - 3], v, a3);
        }
        int t = t0 + tt;
        float v0 = (a0 - bact) * inv_mc, v1 = (a1 - bact) * inv_mc;
        float v2 = (a2 - bact) * inv_mc, v3 = (a3 - bact) * inv_mc;
        if (t + 3 < T) {
            *(float4*)(myrow + t) = make_float4(v0, v1, v2, v3);
        } else {
            if (t + 0 < T) myrow[t + 0] = v0;
            if (t + 1 < T) myrow[t + 1] = v1;
            if (t + 2 < T) myrow[t + 2] = v2;
            if (t + 3 < T) myrow[t + 3] = v3;
        }
    }
}

// ---------------------------------------------------------------------------
// Kernel B: 8 lanes/element systolic ring, patch-at-consume (shfl off-chain),
// tanh.approx activation. Lane r owns taps j=8r+1..8r+8, ring R[8].
//  - consume: valF = fma(Wp, fbPrev, R[p])  (Wp = w_{8r+1} on lanes r>0; the
//    previous step's broadcast supplies the d=1 tap -> no shfl on the chain)
//  - lane0's d=1 tap goes through W0z*f_local scatter (pure ALU chain)
//  - hand-off: valF passes down one lane, seeds overwrite slot (8-step slack)
//  - q and f are block-batched (LDG.128 / STG.128), double-buffered, no movs
// ---------------------------------------------------------------------------
#define STEP8(p, qval) { \
    float val_  = R[(p)&7]; \
    float valF_ = fmaf(Wp, fbPrev, val_); \
    float hU_   = __shfl_down_sync(0xffffffffu, valF_, 1, 8); \
    float U_    = hU_ * u7; \
    float xx_   = valF_ + (qval); \
    float u_    = xx_ * xx_; \
    float s1_   = fmaf(c1, xx_, c0); \
    float s2_   = fmaf(c3, xx_, c2); \
    float pv_   = fmaf(u_, s2_, s1_); \
    float th_; asm("tanh.approx.f32 %0, %1;" : "=f"(th_) : "f"(pv_)); \
    float f_    = fmaxf(0.0f, mfr * th_); \
    R[((p)+1)&7] = fmaf(W0z, f_, R[((p)+1)&7]); \
    float fb_   = __shfl_sync(0xffffffffu, f_, 0, 8); \
    fbv[(p)&7]  = f_; \
    R[((p)+2)&7] = fmaf(W[1], fb_, R[((p)+2)&7]); \
    R[((p)+3)&7] = fmaf(W[2], fb_, R[((p)+3)&7]); \
    R[((p)+4)&7] = fmaf(W[3], fb_, R[((p)+4)&7]); \
    R[((p)+5)&7] = fmaf(W[4], fb_, R[((p)+5)&7]); \
    R[((p)+6)&7] = fmaf(W[5], fb_, R[((p)+6)&7]); \
    R[((p)+7)&7] = fmaf(W[6], fb_, R[((p)+7)&7]); \
    R[(p)&7]     = fmaf(W[7], fb_, U_); \
    fbPrev = fb_; \
}

#define S8(qa, qb) STEP8(0,(qa).x) STEP8(1,(qa).y) STEP8(2,(qa).z) STEP8(3,(qa).w) \
                   STEP8(4,(qb).x) STEP8(5,(qb).y) STEP8(6,(qb).z) STEP8(7,(qb).w)

#define EMIT() if (r == 0) { \
        *(float4*)(optr + 0) = make_float4(fbv[0], fbv[1], fbv[2], fbv[3]); \
        *(float4*)(optr + 4) = make_float4(fbv[4], fbv[5], fbv[6], fbv[7]); \
    } \
    optr += 8;

__global__ void __launch_bounds__(128) rec_kernel(
    const float* __restrict__ b_lag,
    const float* __restrict__ poly_coeff,
    const float* __restrict__ max_cur,
    const float* __restrict__ max_fr,
    int T)
{
    const int tid = threadIdx.x;
    const int r   = tid & 7;                        // lane within 8-lane group
    const int e   = blockIdx.x * 16 + (tid >> 3);   // element index

    const float inv_mc = 1.0f / __ldg(&max_cur[0]);
    const float mfr    = __ldg(&max_fr[0]);
    float c0 = __ldg(&poly_coeff[0]); c0 *= c0;
    float c1 = __ldg(&poly_coeff[1]); c1 *= c1;
    float c2 = __ldg(&poly_coeff[2]); c2 *= c2;
    float c3 = __ldg(&poly_coeff[3]); c3 *= c3;
    const float cw = 1000.0f * inv_mc;

    // lane r owns taps j = 8r+d (d=1..8); W[d-1] = cw * b_lag[64 - j]
    float W[8];
#pragma unroll
    for (int d = 1; d <= 8; ++d) W[d - 1] = cw * __ldg(&b_lag[64 - 8 * r - d]);

    const float W0z = (r == 0) ? W[0] : 0.0f;   // lane0: d=1 via local f
    const float Wp  = (r == 0) ? 0.0f : W[0];   // lanes>0: d=1 via consume patch
    const float u7  = (r == 7) ? 0.0f : 1.0f;   // hand-off mask

    float R[8];
#pragma unroll
    for (int k = 0; k < 8; ++k) R[k] = 0.0f;
    float fbv[8];
    float fbPrev = 0.0f;

    const float4* qrow = (const float4*)(g_qxT + (size_t)e * TR);
    float* optr = g_outT + (size_t)e * TROUT;

    float4 qa = __ldg(qrow + 0), qb = __ldg(qrow + 1);

    const int nfull = T >> 3;
    const int npair = nfull >> 1;
    for (int m = 0; m < npair; ++m) {
        float4 na = __ldg(qrow + (size_t)(4 * m) + 2);
        float4 nb = __ldg(qrow + (size_t)(4 * m) + 3);
        S8(qa, qb)
        EMIT()
        qa = __ldg(qrow + (size_t)(4 * m) + 4);
        qb = __ldg(qrow + (size_t)(4 * m) + 5);
        S8(na, nb)
        EMIT()
    }
    if (nfull & 1) {                 // odd leftover 8-block
        S8(qa, qb)
        EMIT()
    }

    // ---- generic tail (T mod 8 steps; T=2000 -> empty) ----
    const int t0tail = nfull * 8;
    const int tail   = T - t0tail;
    if (tail > 0) {
        float ringD[8];
#pragma unroll
        for (int k = 0; k < 8; ++k) ringD[k] = R[k];
#pragma unroll 1
        for (int tt = 0; tt < tail; ++tt) {
            int t = t0tail + tt;
            int p = t & 7;
            float val  = ringD[p];
            float valF = fmaf(Wp, fbPrev, val);
            float hU   = __shfl_down_sync(0xffffffffu, valF, 1, 8);
            float U    = hU * u7;
            float xx   = valF + __ldg(g_qxT + (size_t)e * TR + t);
            float u_   = xx * xx;
            float s1_  = fmaf(c1, xx, c0);
            float s2_  = fmaf(c3, xx, c2);
            float pv   = fmaf(u_, s2_, s1_);
            float th; asm("tanh.approx.f32 %0, %1;" : "=f"(th) : "f"(pv));
            float f = fmaxf(0.0f, mfr * th);
            ringD[(p + 1) & 7] = fmaf(W0z, f, ringD[(p + 1) & 7]);
            float fb = __shfl_sync(0xffffffffu, f, 0, 8);
            if (r == 0) g_outT[(size_t)e * TROUT + t] = f;
#pragma unroll 1
            for (int d = 2; d <= 7; ++d)
                ringD[(p + d) & 7] = fmaf(W[d - 1], fb, ringD[(p + d) & 7]);
            ringD[p] = fmaf(W[7], fb, U);
            fbPrev = fb;
        }
    }
}

// ---------------------------------------------------------------------------
// Kernel C: transpose g_outT[e][t] -> out[t][e]
// ---------------------------------------------------------------------------
__global__ void __launch_bounds__(256) tr_kernel(float* __restrict__ out, int T)
{
    __shared__ float tile[32][33];
    const int tx = threadIdx.x, ty = threadIdx.y;   // 32 x 8
    const int e0 = blockIdx.x * 32;
    const int t0 = blockIdx.y * 32;

#pragma unroll
    for (int j = 0; j < 4; ++j) {
        int e = e0 + ty + 8 * j;
        int t = t0 + tx;
        tile[ty + 8 * j][tx] = (t < T) ? g_outT[(size_t)e * TROUT + t] : 0.0f;
    }
    __syncthreads();
#pragma unroll
    for (int j = 0; j < 4; ++j) {
        int t = t0 + ty + 8 * j;
        if (t < T) out[(size_t)t * BB + e0 + tx] = tile[tx][ty + 8 * j];
    }
}

// ---------------------------------------------------------------------------
extern "C" void kernel_launch(void* const* d_in, const int* in_sizes, int n_in,
                              void* d_out, int out_size)
{
    const float* currents = (const float*)d_in[0];
    const float* a        = (const float*)d_in[1];
    const float* b_lag    = (const float*)d_in[2];
    const float* poly     = (const float*)d_in[3];
    const float* b_act    = (const float*)d_in[4];
    const float* max_cur  = (const float*)d_in[5];
    const float* max_fr   = (const float*)d_in[6];
    float* out = (float*)d_out;

    const int T = in_sizes[0] / BB;   // 2000

    dim3 gA(BB / 64, (T + 63) / 64);
    fir_kernel<<<gA, 64>>>(currents, a, b_act, max_cur, T);

    // 8 lanes/element, 16 elements per 128-thread block -> 128 blocks
    rec_kernel<<<BB / 16, 128>>>(b_lag, poly, max_cur, max_fr, T);

    dim3 gC(BB / 32, (T + 31) / 32);
    tr_kernel<<<gC, dim3(32, 8)>>>(out, T);
}

// round 8
// speedup vs baseline: 1.9697x; 1.2717x over previous
#include <cuda_runtime.h>

#define BB    2048
#define TR    2080   // row length of transposed qx (floats); rows zero-padded
#define TROUT 2048   // row length of transposed output

// transposed FIR output: g_qxT[e*TR + t] = (x[t,e]-b_act)/max_current
__device__ float g_qxT[(size_t)BB * TR];
// transposed recurrence output: g_outT[e*TROUT + t] = f[t,e]
__device__ float g_outT[(size_t)BB * TROUT];

// ---------------------------------------------------------------------------
// Kernel A: FIR pre-pass, transposed output. Rebuilt for FMA saturation:
// block = 128 threads = 64 e-columns x 2 t-halves; t-tile 128 (smem 191 rows);
// per thread 8 groups of 8 outputs; inner iteration = 1 LDS + 8 FMA.
// ---------------------------------------------------------------------------
__global__ void __launch_bounds__(128) fir_kernel(
    const float* __restrict__ cur,
    const float* __restrict__ a,
    const float* __restrict__ b_act,
    const float* __restrict__ max_cur,
    int T)
{
    __shared__ float sm[191][64];      // rows t0-63 .. t0+127
    const int li = threadIdx.x & 63;   // e-lane
    const int th = threadIdx.x >> 6;   // t-half (0/1)
    const int i  = blockIdx.x * 64 + li;
    const int t0 = blockIdx.y * 128;

    float areg[64];
#pragma unroll
    for (int k = 0; k < 64; ++k) areg[k] = __ldg(&a[k]);
    const float bact   = __ldg(&b_act[0]);
    const float inv_mc = 1.0f / __ldg(&max_cur[0]);

    // cooperative fill: the two t-halves stripe the 191 rows
#pragma unroll 4
    for (int rr = th; rr < 191; rr += 2) {
        int s = t0 - 63 + rr;
        sm[rr][li] = (s >= 0 && s < T) ? __ldg(&cur[(size_t)s * BB + i]) : 0.0f;
    }
    __syncthreads();

    float* myrow = g_qxT + (size_t)i * TR;
    const int tb = th * 64;            // this thread's t-offset within tile

#pragma unroll 1
    for (int g = 0; g < 8; ++g) {
        const int tt = tb + g * 8;     // 0..184; max smem row touched = 184+70=190 ✓
        float acc[8];
#pragma unroll
        for (int o = 0; o < 8; ++o) acc[o] = 0.0f;

#pragma unroll
        for (int rr = 0; rr < 71; ++rr) {
            float v = sm[tt + rr][li];
#pragma unroll
            for (int o = 0; o < 8; ++o)
                if (rr >= o && rr <= o + 63)
                    acc[o] = fmaf(areg[rr - o], v, acc[o]);
        }

        const int t = t0 + tt;
        float r0 = (acc[0] - bact) * inv_mc, r1 = (acc[1] - bact) * inv_mc;
        float r2 = (acc[2] - bact) * inv_mc, r3 = (acc[3] - bact) * inv_mc;
        float r4 = (acc[4] - bact) * inv_mc, r5 = (acc[5] - bact) * inv_mc;
        float r6 = (acc[6] - bact) * inv_mc, r7 = (acc[7] - bact) * inv_mc;
        if (t + 7 < T) {
            *(float4*)(myrow + t)     = make_float4(r0, r1, r2, r3);
            *(float4*)(myrow + t + 4) = make_float4(r4, r5, r6, r7);
        } else {
            if (t + 0 < T) myrow[t + 0] = r0;
            if (t + 1 < T) myrow[t + 1] = r1;
            if (t + 2 < T) myrow[t + 2] = r2;
            if (t + 3 < T) myrow[t + 3] = r3;
            if (t + 4 < T) myrow[t + 4] = r4;
            if (t + 5 < T) myrow[t + 5] = r5;
            if (t + 6 < T) myrow[t + 6] = r6;
            if (t + 7 < T) myrow[t + 7] = r7;
        }
    }
}

// ---------------------------------------------------------------------------
// Kernel B: 8 lanes/element systolic ring, patch-at-consume (shfl off-chain),
// tanh.approx activation. UNCHANGED from round 7.
// ---------------------------------------------------------------------------
#define STEP8(p, qval) { \
    float val_  = R[(p)&7]; \
    float valF_ = fmaf(Wp, fbPrev, val_); \
    float hU_   = __shfl_down_sync(0xffffffffu, valF_, 1, 8); \
    float U_    = hU_ * u7; \
    float xx_   = valF_ + (qval); \
    float u_    = xx_ * xx_; \
    float s1_   = fmaf(c1, xx_, c0); \
    float s2_   = fmaf(c3, xx_, c2); \
    float pv_   = fmaf(u_, s2_, s1_); \
    float th_; asm("tanh.approx.f32 %0, %1;" : "=f"(th_) : "f"(pv_)); \
    float f_    = fmaxf(0.0f, mfr * th_); \
    R[((p)+1)&7] = fmaf(W0z, f_, R[((p)+1)&7]); \
    float fb_   = __shfl_sync(0xffffffffu, f_, 0, 8); \
    fbv[(p)&7]  = f_; \
    R[((p)+2)&7] = fmaf(W[1], fb_, R[((p)+2)&7]); \
    R[((p)+3)&7] = fmaf(W[2], fb_, R[((p)+3)&7]); \
    R[((p)+4)&7] = fmaf(W[3], fb_, R[((p)+4)&7]); \
    R[((p)+5)&7] = fmaf(W[4], fb_, R[((p)+5)&7]); \
    R[((p)+6)&7] = fmaf(W[5], fb_, R[((p)+6)&7]); \
    R[((p)+7)&7] = fmaf(W[6], fb_, R[((p)+7)&7]); \
    R[(p)&7]     = fmaf(W[7], fb_, U_); \
    fbPrev = fb_; \
}

#define S8(qa, qb) STEP8(0,(qa).x) STEP8(1,(qa).y) STEP8(2,(qa).z) STEP8(3,(qa).w) \
                   STEP8(4,(qb).x) STEP8(5,(qb).y) STEP8(6,(qb).z) STEP8(7,(qb).w)

#define EMIT() if (r == 0) { \
        *(float4*)(optr + 0) = make_float4(fbv[0], fbv[1], fbv[2], fbv[3]); \
        *(float4*)(optr + 4) = make_float4(fbv[4], fbv[5], fbv[6], fbv[7]); \
    } \
    optr += 8;

__global__ void __launch_bounds__(128) rec_kernel(
    const float* __restrict__ b_lag,
    const float* __restrict__ poly_coeff,
    const float* __restrict__ max_cur,
    const float* __restrict__ max_fr,
    int T)
{
    const int tid = threadIdx.x;
    const int r   = tid & 7;
    const int e   = blockIdx.x * 16 + (tid >> 3);

    const float inv_mc = 1.0f / __ldg(&max_cur[0]);
    const float mfr    = __ldg(&max_fr[0]);
    float c0 = __ldg(&poly_coeff[0]); c0 *= c0;
    float c1 = __ldg(&poly_coeff[1]); c1 *= c1;
    float c2 = __ldg(&poly_coeff[2]); c2 *= c2;
    float c3 = __ldg(&poly_coeff[3]); c3 *= c3;
    const float cw = 1000.0f * inv_mc;

    float W[8];
#pragma unroll
    for (int d = 1; d <= 8; ++d) W[d - 1] = cw * __ldg(&b_lag[64 - 8 * r - d]);

    const float W0z = (r == 0) ? W[0] : 0.0f;
    const float Wp  = (r == 0) ? 0.0f : W[0];
    const float u7  = (r == 7) ? 0.0f : 1.0f;

    float R[8];
#pragma unroll
    for (int k = 0; k < 8; ++k) R[k] = 0.0f;
    float fbv[8];
    float fbPrev = 0.0f;

    const float4* qrow = (const float4*)(g_qxT + (size_t)e * TR);
    float* optr = g_outT + (size_t)e * TROUT;

    float4 qa = __ldg(qrow + 0), qb = __ldg(qrow + 1);

    const int nfull = T >> 3;
    const int npair = nfull >> 1;
    for (int m = 0; m < npair; ++m) {
        float4 na = __ldg(qrow + (size_t)(4 * m) + 2);
        float4 nb = __ldg(qrow + (size_t)(4 * m) + 3);
        S8(qa, qb)
        EMIT()
        qa = __ldg(qrow + (size_t)(4 * m) + 4);
        qb = __ldg(qrow + (size_t)(4 * m) + 5);
        S8(na, nb)
        EMIT()
    }
    if (nfull & 1) {
        S8(qa, qb)
        EMIT()
    }

    const int t0tail = nfull * 8;
    const int tail   = T - t0tail;
    if (tail > 0) {
        float ringD[8];
#pragma unroll
        for (int k = 0; k < 8; ++k) ringD[k] = R[k];
#pragma unroll 1
        for (int tt = 0; tt < tail; ++tt) {
            int t = t0tail + tt;
            int p = t & 7;
            float val  = ringD[p];
            float valF = fmaf(Wp, fbPrev, val);
            float hU   = __shfl_down_sync(0xffffffffu, valF, 1, 8);
            float U    = hU * u7;
            float xx   = valF + __ldg(g_qxT + (size_t)e * TR + t);
            float u_   = xx * xx;
            float s1_  = fmaf(c1, xx, c0);
            float s2_  = fmaf(c3, xx, c2);
            float pv   = fmaf(u_, s2_, s1_);
            float th; asm("tanh.approx.f32 %0, %1;" : "=f"(th) : "f"(pv));
            float f = fmaxf(0.0f, mfr * th);
            ringD[(p + 1) & 7] = fmaf(W0z, f, ringD[(p + 1) & 7]);
            float fb = __shfl_sync(0xffffffffu, f, 0, 8);
            if (r == 0) g_outT[(size_t)e * TROUT + t] = f;
#pragma unroll 1
            for (int d = 2; d <= 7; ++d)
                ringD[(p + d) & 7] = fmaf(W[d - 1], fb, ringD[(p + d) & 7]);
            ringD[p] = fmaf(W[7], fb, U);
            fbPrev = fb;
        }
    }
}

// ---------------------------------------------------------------------------
// Kernel C: transpose g_outT[e][t] -> out[t][e]  (unchanged)
// ---------------------------------------------------------------------------
__global__ void __launch_bounds__(256) tr_kernel(float* __restrict__ out, int T)
{
    __shared__ float tile[32][33];
    const int tx = threadIdx.x, ty = threadIdx.y;   // 32 x 8
    const int e0 = blockIdx.x * 32;
    const int t0 = blockIdx.y * 32;

#pragma unroll
    for (int j = 0; j < 4; ++j) {
        int e = e0 + ty + 8 * j;
        int t = t0 + tx;
        tile[ty + 8 * j][tx] = (t < T) ? g_outT[(size_t)e * TROUT + t] : 0.0f;
    }
    __syncthreads();
#pragma unroll
    for (int j = 0; j < 4; ++j) {
        int t = t0 + ty + 8 * j;
        if (t < T) out[(size_t)t * BB + e0 + tx] = tile[tx][ty + 8 * j];
    }
}

// ---------------------------------------------------------------------------
extern "C" void kernel_launch(void* const* d_in, const int* in_sizes, int n_in,
                              void* d_out, int out_size)
{
    const float* currents = (const float*)d_in[0];
    const float* a        = (const float*)d_in[1];
    const float* b_lag    = (const float*)d_in[2];
    const float* poly     = (const float*)d_in[3];
    const float* b_act    = (const float*)d_in[4];
    const float* max_cur  = (const float*)d_in[5];
    const float* max_fr   = (const float*)d_in[6];
    float* out = (float*)d_out;

    const int T = in_sizes[0] / BB;   // 2000

    dim3 gA(BB / 64, (T + 127) / 128);
    fir_kernel<<<gA, 128>>>(currents, a, b_act, max_cur, T);

    rec_kernel<<<BB / 16, 128>>>(b_lag, poly, max_cur, max_fr, T);

    dim3 gC(BB / 32, (T + 31) / 32);
    tr_kernel<<<gC, dim3(32, 8)>>>(out, T);
}